// round 2
// baseline (speedup 1.0000x reference)
#include <cuda_runtime.h>
#include <math.h>

// ---------------------------------------------------------------------------
// LiquidNCPNetwork: 32-step scan over 3 chained CfC cells.
//   cell1: z=[x_t(512), h1(1229)] K=1741 -> N=1229
//   cell2: z=[o1(1229), h2(819)]  K=2048 -> N=819
//   cell3: z=[o2(819),  h3(512)]  K=1331 -> N=512
// out = concat(y_pred (64,32,512), h_final (64,2560)) as float32.
//
// R1: fp32 SIMT, head-interleaved weights. prep folds mask, transposes to
// [k][j] and interleaves the 4 heads as float4 (one LDG.128 per k per col),
// with K zero-padded to a multiple of 32 (tail-free mainloop). Cell tiles are
// 32 rows x 8 cols x 4 heads per 128-thread block -> 308/206/128 blocks.
// ---------------------------------------------------------------------------

#define BATCH  64
#define SEQ    32
#define IN_F   512
#define INTER  1229
#define CMD    819
#define MOTOR  512
#define NUNITS 2560

#define K1 1741
#define N1 1229
#define K2 2048
#define N2 819
#define K3 1331
#define N3 512

#define KT 32
#define K1P 1760   // ceil(K1/32)*32
#define K2P 2048
#define K3P 1344

// masked weights, head-interleaved: w4[k*N + j] = {Wg,Wh,Wfg,Wfh}(j,k)*M(j,k)
__device__ float4 g_w1[(size_t)K1P * N1];
__device__ float4 g_w2[(size_t)K2P * N2];
__device__ float4 g_w3[(size_t)K3P * N3];
// ping-pong hidden state [2][B][NUNITS]
__device__ float g_hbuf[2][BATCH * NUNITS];

// ---------------------------------------------------------------------------
// prep: dst[k][j] = float4(Wg,Wh,Wfg,Wfh)[j][k] * M[j][k]; zero for K<=k<Kpad.
// ---------------------------------------------------------------------------
__global__ void prep4_kernel(const float* __restrict__ Wg, const float* __restrict__ Wh,
                             const float* __restrict__ Wfg, const float* __restrict__ Wfh,
                             const float* __restrict__ M, float4* __restrict__ dst,
                             int K, int N, int Kpad)
{
    __shared__ float4 tile[32][33];
    int k0 = blockIdx.x * 32, j0 = blockIdx.y * 32;
    int tx = threadIdx.x, ty = threadIdx.y;   // 32 x 8
    #pragma unroll
    for (int i = 0; i < 32; i += 8) {
        int j = j0 + ty + i, k = k0 + tx;
        float4 v = make_float4(0.f, 0.f, 0.f, 0.f);
        if (j < N && k < K) {
            size_t idx = (size_t)j * K + k;
            float m = M[idx];
            v = make_float4(Wg[idx] * m, Wh[idx] * m, Wfg[idx] * m, Wfh[idx] * m);
        }
        tile[ty + i][tx] = v;
    }
    __syncthreads();
    #pragma unroll
    for (int i = 0; i < 32; i += 8) {
        int k = k0 + ty + i, j = j0 + tx;
        if (k < Kpad && j < N) dst[(size_t)k * N + j] = tile[tx][ty + i];
    }
}

// ---------------------------------------------------------------------------
// cell: tile = 32 rows (blockIdx.y half of batch) x 8 cols x 4 heads.
// 128 threads: tx = col (0..7), ty = row pair (0..15), 2 rows per thread.
// acc[4 heads][2 rows]. z tile (32 x KT) staged in smem (stride 36: float4-
// aligned, bank-conflict-free). Weights stream as one LDG.128 per (k, col).
// ---------------------------------------------------------------------------
__global__ void __launch_bounds__(128)
cell_kernel(
    const float* __restrict__ A,  int lda, int Kx,   // x-part rows (B x Kx)
    const float* __restrict__ Hp, int ldh,           // h-part rows
    const float4* __restrict__ W4,                   // [Kpad][N] interleaved
    const float* __restrict__ bg, const float* __restrict__ bh,
    const float* __restrict__ bfg, const float* __restrict__ bfh,
    const float* __restrict__ tsp, int sidx,
    int K, int Kpad, int N,
    float* __restrict__ o_out,                       // row stride NUNITS
    float* __restrict__ y_out)                       // optional y slice
{
    __shared__ float zs[32][36];
    int tid = threadIdx.x;
    int tx  = tid & 7;
    int ty  = tid >> 3;              // 0..15
    int r0  = ty * 2;
    int row_base = blockIdx.y * 32;
    int j   = blockIdx.x * 8 + tx;
    int jc  = (j < N) ? j : (N - 1);

    float acc[4][2];
    #pragma unroll
    for (int t = 0; t < 4; t++) { acc[t][0] = 0.f; acc[t][1] = 0.f; }

    for (int k0 = 0; k0 < Kpad; k0 += KT) {
        // cooperative z-tile load (coalesced along k; zero beyond K)
        #pragma unroll
        for (int l = 0; l < 8; l++) {
            int idx = tid + l * 128;
            int row = idx >> 5;
            int kk  = idx & 31;
            int k   = k0 + kk;
            float v = 0.f;
            if (k < Kx)      v = A[(size_t)(row_base + row) * lda + k];
            else if (k < K)  v = Hp[(size_t)(row_base + row) * ldh + (k - Kx)];
            zs[row][kk] = v;
        }
        __syncthreads();

        const float4* wp = W4 + (size_t)k0 * N + jc;
        #pragma unroll 8
        for (int kk = 0; kk < KT; kk += 4) {
            float4 z0 = *(const float4*)&zs[r0][kk];
            float4 z1 = *(const float4*)&zs[r0 + 1][kk];
            #pragma unroll
            for (int u = 0; u < 4; u++) {
                float4 w = wp[(size_t)(kk + u) * N];
                float zu0 = (u == 0) ? z0.x : (u == 1) ? z0.y : (u == 2) ? z0.z : z0.w;
                float zu1 = (u == 0) ? z1.x : (u == 1) ? z1.y : (u == 2) ? z1.z : z1.w;
                acc[0][0] = fmaf(w.x, zu0, acc[0][0]);
                acc[1][0] = fmaf(w.y, zu0, acc[1][0]);
                acc[2][0] = fmaf(w.z, zu0, acc[2][0]);
                acc[3][0] = fmaf(w.w, zu0, acc[3][0]);
                acc[0][1] = fmaf(w.x, zu1, acc[0][1]);
                acc[1][1] = fmaf(w.y, zu1, acc[1][1]);
                acc[2][1] = fmaf(w.z, zu1, acc[2][1]);
                acc[3][1] = fmaf(w.w, zu1, acc[3][1]);
            }
        }
        __syncthreads();
    }

    if (j < N) {
        float ts  = tsp[sidx];
        float vbg = bg[j], vbh = bh[j], vbfg = bfg[j], vbfh = bfh[j];
        #pragma unroll
        for (int i = 0; i < 2; i++) {
            int row = row_base + r0 + i;
            float g    = tanhf(acc[0][i] + vbg);
            float hh   = tanhf(acc[1][i] + vbh);
            float pre  = (acc[2][i] + vbfg) + ts * (acc[3][i] + vbfh);
            float gate = 1.f / (1.f + expf(-pre));
            float o    = g * (1.f - gate) + hh * gate;
            o_out[(size_t)row * NUNITS + j] = o;
            if (y_out)
                y_out[(size_t)row * (SEQ * MOTOR) + (size_t)sidx * MOTOR + j] = o;
        }
    }
}

// ---------------------------------------------------------------------------
extern "C" void kernel_launch(void* const* d_in, const int* in_sizes, int n_in,
                              void* d_out, int out_size)
{
    const float* x   = (const float*)d_in[0];
    const float* h0  = (const float*)d_in[1];
    const float* ts  = (const float*)d_in[2];

    const float* Wg1 = (const float*)d_in[3];
    const float* Wh1 = (const float*)d_in[4];
    const float* Wfg1= (const float*)d_in[5];
    const float* Wfh1= (const float*)d_in[6];
    const float* bg1 = (const float*)d_in[7];
    const float* bh1 = (const float*)d_in[8];
    const float* bfg1= (const float*)d_in[9];
    const float* bfh1= (const float*)d_in[10];
    const float* m1  = (const float*)d_in[11];

    const float* Wg2 = (const float*)d_in[12];
    const float* Wh2 = (const float*)d_in[13];
    const float* Wfg2= (const float*)d_in[14];
    const float* Wfh2= (const float*)d_in[15];
    const float* bg2 = (const float*)d_in[16];
    const float* bh2 = (const float*)d_in[17];
    const float* bfg2= (const float*)d_in[18];
    const float* bfh2= (const float*)d_in[19];
    const float* m2  = (const float*)d_in[20];

    const float* Wg3 = (const float*)d_in[21];
    const float* Wh3 = (const float*)d_in[22];
    const float* Wfg3= (const float*)d_in[23];
    const float* Wfh3= (const float*)d_in[24];
    const float* bg3 = (const float*)d_in[25];
    const float* bh3 = (const float*)d_in[26];
    const float* bfg3= (const float*)d_in[27];
    const float* bfh3= (const float*)d_in[28];
    const float* m3  = (const float*)d_in[29];

    float* out = (float*)d_out;

    float4 *w1p, *w2p, *w3p;
    float *hb;
    cudaGetSymbolAddress((void**)&w1p, g_w1);
    cudaGetSymbolAddress((void**)&w2p, g_w2);
    cudaGetSymbolAddress((void**)&w3p, g_w3);
    cudaGetSymbolAddress((void**)&hb,  g_hbuf);

    dim3 pb(32, 8);
    prep4_kernel<<<dim3(K1P / 32, (N1 + 31) / 32), pb>>>(Wg1, Wh1, Wfg1, Wfh1, m1, w1p, K1, N1, K1P);
    prep4_kernel<<<dim3(K2P / 32, (N2 + 31) / 32), pb>>>(Wg2, Wh2, Wfg2, Wfh2, m2, w2p, K2, N2, K2P);
    prep4_kernel<<<dim3(K3P / 32, (N3 + 31) / 32), pb>>>(Wg3, Wh3, Wfg3, Wfh3, m3, w3p, K3, N3, K3P);

    cudaMemcpyAsync(hb, h0, sizeof(float) * BATCH * NUNITS,
                    cudaMemcpyDeviceToDevice, 0);

    int p = 0;
    for (int s = 0; s < SEQ; s++) {
        float* hprev = hb + (size_t)p * BATCH * NUNITS;
        float* hnext = hb + (size_t)(1 - p) * BATCH * NUNITS;
        const float* xt = x + (size_t)s * IN_F;   // row stride SEQ*IN_F

        cell_kernel<<<dim3((N1 + 7) / 8, 2), 128>>>(
            xt, SEQ * IN_F, IN_F, hprev, NUNITS,
            w1p, bg1, bh1, bfg1, bfh1, ts, s, K1, K1P, N1,
            hnext, nullptr);

        cell_kernel<<<dim3((N2 + 7) / 8, 2), 128>>>(
            hnext, NUNITS, INTER, hprev + INTER, NUNITS,
            w2p, bg2, bh2, bfg2, bfh2, ts, s, K2, K2P, N2,
            hnext + INTER, nullptr);

        cell_kernel<<<dim3((N3 + 7) / 8, 2), 128>>>(
            hnext + INTER, NUNITS, CMD, hprev + INTER + CMD, NUNITS,
            w3p, bg3, bh3, bfg3, bfh3, ts, s, K3, K3P, N3,
            hnext + INTER + CMD, out);

        p ^= 1;
    }

    // after 32 flips p==0: final state is in buffer 0
    cudaMemcpyAsync(out + (size_t)BATCH * SEQ * MOTOR, hb,
                    sizeof(float) * BATCH * NUNITS,
                    cudaMemcpyDeviceToDevice, 0);
}

// round 3
// speedup vs baseline: 1.1083x; 1.1083x over previous
#include <cuda_runtime.h>
#include <math.h>

// ---------------------------------------------------------------------------
// LiquidNCPNetwork: 32-step scan over 3 chained CfC cells.
//   cell1: z=[x_t(512), h1(1229)] K=1741 -> N=1229
//   cell2: z=[o1(1229), h2(819)]  K=2048 -> N=819
//   cell3: z=[o2(819),  h3(512)]  K=1331 -> N=512
// out = concat(y_pred (64,32,512), h_final (64,2560)) as float32.
//
// R1: fp32 SIMT, head-interleaved weights. prep folds mask, transposes to
// [k][j] and interleaves the 4 heads as float4 (one LDG.128 per k per col),
// with K zero-padded to a multiple of 32 (tail-free mainloop). Cell tiles are
// 32 rows x 8 cols x 4 heads per 128-thread block -> 308/206/128 blocks.
// ---------------------------------------------------------------------------

#define BATCH  64
#define SEQ    32
#define IN_F   512
#define INTER  1229
#define CMD    819
#define MOTOR  512
#define NUNITS 2560

#define K1 1741
#define N1 1229
#define K2 2048
#define N2 819
#define K3 1331
#define N3 512

#define KT 32
#define K1P 1760   // ceil(K1/32)*32
#define K2P 2048
#define K3P 1344

// masked weights, head-interleaved: w4[k*N + j] = {Wg,Wh,Wfg,Wfh}(j,k)*M(j,k)
__device__ float4 g_w1[(size_t)K1P * N1];
__device__ float4 g_w2[(size_t)K2P * N2];
__device__ float4 g_w3[(size_t)K3P * N3];
// ping-pong hidden state [2][B][NUNITS]
__device__ float g_hbuf[2][BATCH * NUNITS];

// ---------------------------------------------------------------------------
// prep: dst[k][j] = float4(Wg,Wh,Wfg,Wfh)[j][k] * M[j][k]; zero for K<=k<Kpad.
// ---------------------------------------------------------------------------
__global__ void prep4_kernel(const float* __restrict__ Wg, const float* __restrict__ Wh,
                             const float* __restrict__ Wfg, const float* __restrict__ Wfh,
                             const float* __restrict__ M, float4* __restrict__ dst,
                             int K, int N, int Kpad)
{
    __shared__ float4 tile[32][33];
    int k0 = blockIdx.x * 32, j0 = blockIdx.y * 32;
    int tx = threadIdx.x, ty = threadIdx.y;   // 32 x 8
    #pragma unroll
    for (int i = 0; i < 32; i += 8) {
        int j = j0 + ty + i, k = k0 + tx;
        float4 v = make_float4(0.f, 0.f, 0.f, 0.f);
        if (j < N && k < K) {
            size_t idx = (size_t)j * K + k;
            float m = M[idx];
            v = make_float4(Wg[idx] * m, Wh[idx] * m, Wfg[idx] * m, Wfh[idx] * m);
        }
        tile[ty + i][tx] = v;
    }
    __syncthreads();
    #pragma unroll
    for (int i = 0; i < 32; i += 8) {
        int k = k0 + ty + i, j = j0 + tx;
        if (k < Kpad && j < N) dst[(size_t)k * N + j] = tile[tx][ty + i];
    }
}

// ---------------------------------------------------------------------------
// cell: tile = 32 rows (blockIdx.y half of batch) x 8 cols x 4 heads.
// 128 threads: tx = col (0..7), ty = row pair (0..15), 2 rows per thread.
// acc[4 heads][2 rows]. z tile (32 x KT) staged in smem (stride 36: float4-
// aligned, bank-conflict-free). Weights stream as one LDG.128 per (k, col).
// ---------------------------------------------------------------------------
__global__ void __launch_bounds__(128)
cell_kernel(
    const float* __restrict__ A,  int lda, int Kx,   // x-part rows (B x Kx)
    const float* __restrict__ Hp, int ldh,           // h-part rows
    const float4* __restrict__ W4,                   // [Kpad][N] interleaved
    const float* __restrict__ bg, const float* __restrict__ bh,
    const float* __restrict__ bfg, const float* __restrict__ bfh,
    const float* __restrict__ tsp, int sidx,
    int K, int Kpad, int N,
    float* __restrict__ o_out,                       // row stride NUNITS
    float* __restrict__ y_out)                       // optional y slice
{
    __shared__ float zs[32][36];
    int tid = threadIdx.x;
    int tx  = tid & 7;
    int ty  = tid >> 3;              // 0..15
    int r0  = ty * 2;
    int row_base = blockIdx.y * 32;
    int j   = blockIdx.x * 8 + tx;
    int jc  = (j < N) ? j : (N - 1);

    float acc[4][2];
    #pragma unroll
    for (int t = 0; t < 4; t++) { acc[t][0] = 0.f; acc[t][1] = 0.f; }

    for (int k0 = 0; k0 < Kpad; k0 += KT) {
        // cooperative z-tile load (coalesced along k; zero beyond K)
        #pragma unroll
        for (int l = 0; l < 8; l++) {
            int idx = tid + l * 128;
            int row = idx >> 5;
            int kk  = idx & 31;
            int k   = k0 + kk;
            float v = 0.f;
            if (k < Kx)      v = A[(size_t)(row_base + row) * lda + k];
            else if (k < K)  v = Hp[(size_t)(row_base + row) * ldh + (k - Kx)];
            zs[row][kk] = v;
        }
        __syncthreads();

        const float4* wp = W4 + (size_t)k0 * N + jc;
        #pragma unroll 8
        for (int kk = 0; kk < KT; kk += 4) {
            float4 z0 = *(const float4*)&zs[r0][kk];
            float4 z1 = *(const float4*)&zs[r0 + 1][kk];
            #pragma unroll
            for (int u = 0; u < 4; u++) {
                float4 w = wp[(size_t)(kk + u) * N];
                float zu0 = (u == 0) ? z0.x : (u == 1) ? z0.y : (u == 2) ? z0.z : z0.w;
                float zu1 = (u == 0) ? z1.x : (u == 1) ? z1.y : (u == 2) ? z1.z : z1.w;
                acc[0][0] = fmaf(w.x, zu0, acc[0][0]);
                acc[1][0] = fmaf(w.y, zu0, acc[1][0]);
                acc[2][0] = fmaf(w.z, zu0, acc[2][0]);
                acc[3][0] = fmaf(w.w, zu0, acc[3][0]);
                acc[0][1] = fmaf(w.x, zu1, acc[0][1]);
                acc[1][1] = fmaf(w.y, zu1, acc[1][1]);
                acc[2][1] = fmaf(w.z, zu1, acc[2][1]);
                acc[3][1] = fmaf(w.w, zu1, acc[3][1]);
            }
        }
        __syncthreads();
    }

    if (j < N) {
        float ts  = tsp[sidx];
        float vbg = bg[j], vbh = bh[j], vbfg = bfg[j], vbfh = bfh[j];
        #pragma unroll
        for (int i = 0; i < 2; i++) {
            int row = row_base + r0 + i;
            float g    = tanhf(acc[0][i] + vbg);
            float hh   = tanhf(acc[1][i] + vbh);
            float pre  = (acc[2][i] + vbfg) + ts * (acc[3][i] + vbfh);
            float gate = 1.f / (1.f + expf(-pre));
            float o    = g * (1.f - gate) + hh * gate;
            o_out[(size_t)row * NUNITS + j] = o;
            if (y_out)
                y_out[(size_t)row * (SEQ * MOTOR) + (size_t)sidx * MOTOR + j] = o;
        }
    }
}

// ---------------------------------------------------------------------------
extern "C" void kernel_launch(void* const* d_in, const int* in_sizes, int n_in,
                              void* d_out, int out_size)
{
    const float* x   = (const float*)d_in[0];
    const float* h0  = (const float*)d_in[1];
    const float* ts  = (const float*)d_in[2];

    const float* Wg1 = (const float*)d_in[3];
    const float* Wh1 = (const float*)d_in[4];
    const float* Wfg1= (const float*)d_in[5];
    const float* Wfh1= (const float*)d_in[6];
    const float* bg1 = (const float*)d_in[7];
    const float* bh1 = (const float*)d_in[8];
    const float* bfg1= (const float*)d_in[9];
    const float* bfh1= (const float*)d_in[10];
    const float* m1  = (const float*)d_in[11];

    const float* Wg2 = (const float*)d_in[12];
    const float* Wh2 = (const float*)d_in[13];
    const float* Wfg2= (const float*)d_in[14];
    const float* Wfh2= (const float*)d_in[15];
    const float* bg2 = (const float*)d_in[16];
    const float* bh2 = (const float*)d_in[17];
    const float* bfg2= (const float*)d_in[18];
    const float* bfh2= (const float*)d_in[19];
    const float* m2  = (const float*)d_in[20];

    const float* Wg3 = (const float*)d_in[21];
    const float* Wh3 = (const float*)d_in[22];
    const float* Wfg3= (const float*)d_in[23];
    const float* Wfh3= (const float*)d_in[24];
    const float* bg3 = (const float*)d_in[25];
    const float* bh3 = (const float*)d_in[26];
    const float* bfg3= (const float*)d_in[27];
    const float* bfh3= (const float*)d_in[28];
    const float* m3  = (const float*)d_in[29];

    float* out = (float*)d_out;

    float4 *w1p, *w2p, *w3p;
    float *hb;
    cudaGetSymbolAddress((void**)&w1p, g_w1);
    cudaGetSymbolAddress((void**)&w2p, g_w2);
    cudaGetSymbolAddress((void**)&w3p, g_w3);
    cudaGetSymbolAddress((void**)&hb,  g_hbuf);

    dim3 pb(32, 8);
    prep4_kernel<<<dim3(K1P / 32, (N1 + 31) / 32), pb>>>(Wg1, Wh1, Wfg1, Wfh1, m1, w1p, K1, N1, K1P);
    prep4_kernel<<<dim3(K2P / 32, (N2 + 31) / 32), pb>>>(Wg2, Wh2, Wfg2, Wfh2, m2, w2p, K2, N2, K2P);
    prep4_kernel<<<dim3(K3P / 32, (N3 + 31) / 32), pb>>>(Wg3, Wh3, Wfg3, Wfh3, m3, w3p, K3, N3, K3P);

    cudaMemcpyAsync(hb, h0, sizeof(float) * BATCH * NUNITS,
                    cudaMemcpyDeviceToDevice, 0);

    int p = 0;
    for (int s = 0; s < SEQ; s++) {
        float* hprev = hb + (size_t)p * BATCH * NUNITS;
        float* hnext = hb + (size_t)(1 - p) * BATCH * NUNITS;
        const float* xt = x + (size_t)s * IN_F;   // row stride SEQ*IN_F

        cell_kernel<<<dim3((N1 + 7) / 8, 2), 128>>>(
            xt, SEQ * IN_F, IN_F, hprev, NUNITS,
            w1p, bg1, bh1, bfg1, bfh1, ts, s, K1, K1P, N1,
            hnext, nullptr);

        cell_kernel<<<dim3((N2 + 7) / 8, 2), 128>>>(
            hnext, NUNITS, INTER, hprev + INTER, NUNITS,
            w2p, bg2, bh2, bfg2, bfh2, ts, s, K2, K2P, N2,
            hnext + INTER, nullptr);

        cell_kernel<<<dim3((N3 + 7) / 8, 2), 128>>>(
            hnext + INTER, NUNITS, CMD, hprev + INTER + CMD, NUNITS,
            w3p, bg3, bh3, bfg3, bfh3, ts, s, K3, K3P, N3,
            hnext + INTER + CMD, out);

        p ^= 1;
    }

    // after 32 flips p==0: final state is in buffer 0
    cudaMemcpyAsync(out + (size_t)BATCH * SEQ * MOTOR, hb,
                    sizeof(float) * BATCH * NUNITS,
                    cudaMemcpyDeviceToDevice, 0);
}

// round 6
// speedup vs baseline: 9.2803x; 8.3733x over previous
#include <cuda_runtime.h>
#include <cuda_bf16.h>
#include <math.h>
#include <stdint.h>

// LiquidNCPNetwork via warp-level bf16 mma.sync (compute_103-safe; no tcgen05).
// Per (cell, step, 16-col tile): D[128][128] = A[128][Kc] @ B[128][Kc]^T.
//   A rows 0-63 = z_hi (batch), rows 64-127 = z_lo.
//   B row n = jj*8 + head*2 + part  (part 0 = W_hi, 1 = W_lo), K-major bf16.
//   out(b,jj,head) = D[b][2h] + D[b][2h+1] + D[b+64][2h]   (drop lo*lo).

#define BATCH  64
#define SEQ    32
#define IN_F   512
#define INTER  1229
#define CMD    819
#define MOTOR  512
#define NUNITS 2560
#define YSZ    (BATCH * SEQ * MOTOR)

// chunking: 64-wide K chunks
#define HPAD1 1280
#define KC1   1792
#define XCH1  8
#define HCH1  20
#define XPAD2 1280
#define HPAD2 832
#define KC2   2112
#define XCH2  20
#define HCH2  13
#define XPAD3 832
#define HPAD3 512
#define KC3   1344
#define XCH3  13
#define HCH3  8
#define JT1 77
#define JT2 52
#define JT3 32

__device__ __align__(1024) __nv_bfloat16 g_wb1[(size_t)JT1 * 128 * KC1];
__device__ __align__(1024) __nv_bfloat16 g_wb2[(size_t)JT2 * 128 * KC2];
__device__ __align__(1024) __nv_bfloat16 g_wb3[(size_t)JT3 * 128 * KC3];
__device__ __align__(1024) __nv_bfloat16 g_x1[(size_t)SEQ * 128 * IN_F];
__device__ __align__(1024) __nv_bfloat16 g_z1h[2][128 * HPAD1];
__device__ __align__(1024) __nv_bfloat16 g_z2x[128 * XPAD2];
__device__ __align__(1024) __nv_bfloat16 g_z2h[2][128 * HPAD2];
__device__ __align__(1024) __nv_bfloat16 g_z3x[128 * XPAD3];
__device__ __align__(1024) __nv_bfloat16 g_z3h[2][128 * HPAD3];

#define SW128(o) ((o) ^ (((o) >> 3) & 0x70))
// smem: 2 stages x (A 16KB + B 16KB) = 65536, then S_hi/S_lo 64x68 floats each
#define STAGE_BYTES 32768
#define S_STRIDE    68
#define S_BYTES     (64 * S_STRIDE * 4)
#define SMEM_TOTAL  (2 * STAGE_BYTES + 2 * S_BYTES)

__device__ __forceinline__ uint32_t s2u32(const void* p) {
    uint32_t a;
    asm("{ .reg .u64 t; cvta.to.shared.u64 t, %1; cvt.u32.u64 %0, t; }" : "=r"(a) : "l"(p));
    return a;
}
__device__ __forceinline__ void cpasync16(uint32_t s, const void* g) {
    asm volatile("cp.async.cg.shared.global [%0], [%1], 16;" :: "r"(s), "l"(g));
}
__device__ __forceinline__ void ldm_x4(uint32_t& r0, uint32_t& r1, uint32_t& r2,
                                       uint32_t& r3, uint32_t addr) {
    asm volatile("ldmatrix.sync.aligned.m8n8.x4.shared.b16 {%0,%1,%2,%3}, [%4];"
                 : "=r"(r0), "=r"(r1), "=r"(r2), "=r"(r3) : "r"(addr));
}
__device__ __forceinline__ void mma16816(float* c, uint32_t a0, uint32_t a1, uint32_t a2,
                                         uint32_t a3, uint32_t b0, uint32_t b1) {
    asm volatile("mma.sync.aligned.m16n8k16.row.col.f32.bf16.bf16.f32 "
                 "{%0,%1,%2,%3}, {%4,%5,%6,%7}, {%8,%9}, {%0,%1,%2,%3};"
                 : "+f"(c[0]), "+f"(c[1]), "+f"(c[2]), "+f"(c[3])
                 : "r"(a0), "r"(a1), "r"(a2), "r"(a3), "r"(b0), "r"(b1));
}

// ---------------- prep kernels ----------------
__global__ void prep_w_kernel(const float* __restrict__ Wg, const float* __restrict__ Wh,
                              const float* __restrict__ Wfg, const float* __restrict__ Wfh,
                              const float* __restrict__ M, __nv_bfloat16* __restrict__ dst,
                              int N, int Korig, int xvalid, int xpad, int hvalid, int Kc)
{
    int n = blockIdx.x * 2;
    int loc = n & 127;
    int j = (n >> 7) * 16 + (loc >> 3);
    int t = (loc >> 1) & 3;
    const float* W = (t == 0) ? Wg : (t == 1) ? Wh : (t == 2) ? Wfg : Wfh;
    __nv_bfloat16* d_hi = dst + (size_t)n * Kc;
    __nv_bfloat16* d_lo = d_hi + Kc;
    bool jok = (j < N);
    for (int k = threadIdx.x; k < Kc; k += 256) {
        float v = 0.f;
        if (jok) {
            int kin; bool ok;
            if (k < xpad) { kin = k; ok = (k < xvalid); }
            else { int hk = k - xpad; kin = xvalid + hk; ok = (hk < hvalid); }
            if (ok) v = W[(size_t)j * Korig + kin] * M[(size_t)j * Korig + kin];
        }
        __nv_bfloat16 hi = __float2bfloat16(v);
        d_hi[k] = hi;
        d_lo[k] = __float2bfloat16(v - __bfloat162float(hi));
    }
}

__global__ void prep_x_kernel(const float* __restrict__ x, __nv_bfloat16* __restrict__ dst)
{
    int idx = blockIdx.x * 256 + threadIdx.x;       // < 64*32*512
    int b = idx >> 14, r = idx & 16383, s = r >> 9, f = r & 511;
    float v = x[idx];
    __nv_bfloat16 hi = __float2bfloat16(v);
    size_t base = (size_t)s * 128 * 512;
    dst[base + (size_t)b * 512 + f] = hi;
    dst[base + (size_t)(b + 64) * 512 + f] = __float2bfloat16(v - __bfloat162float(hi));
}

__global__ void prep_h0_kernel(const float* __restrict__ h0, __nv_bfloat16* __restrict__ z1,
                               __nv_bfloat16* __restrict__ z2, __nv_bfloat16* __restrict__ z3)
{
    int idx = blockIdx.x * 256 + threadIdx.x;       // < 64*2560
    int b = idx / NUNITS, u = idx % NUNITS;
    float v = h0[idx];
    __nv_bfloat16 hi = __float2bfloat16(v);
    __nv_bfloat16 lo = __float2bfloat16(v - __bfloat162float(hi));
    if (u < INTER)            { z1[(size_t)b*HPAD1+u] = hi; z1[(size_t)(b+64)*HPAD1+u] = lo; }
    else if (u < INTER + CMD) { int c = u - INTER;
                                z2[(size_t)b*HPAD2+c] = hi; z2[(size_t)(b+64)*HPAD2+c] = lo; }
    else                      { int c = u - INTER - CMD;
                                z3[(size_t)b*HPAD3+c] = hi; z3[(size_t)(b+64)*HPAD3+c] = lo; }
}

// ---------------- cell kernel (warp mma) ----------------
__global__ void __launch_bounds__(256)
cell_mma_kernel(
    const __nv_bfloat16* __restrict__ xpart, int xstride, int xchunks,
    const __nv_bfloat16* __restrict__ hpart, int hstride, int hchunks,
    const __nv_bfloat16* __restrict__ wbase, int wKc,
    const float* __restrict__ bg, const float* __restrict__ bh,
    const float* __restrict__ bfg, const float* __restrict__ bfh,
    const float* __restrict__ tsp, int sidx, int N,
    __nv_bfloat16* __restrict__ znx, int znx_stride,   // next-cell x staging (nullable)
    __nv_bfloat16* __restrict__ zsh, int zsh_stride,   // same-cell h staging [1-p]
    float* __restrict__ yp,                            // cell3 y slice (nullable)
    float* __restrict__ hfp, int hoff)                 // final-h out at s==31 (nullable)
{
    extern __shared__ char smem[];
    const int tid  = threadIdx.x;
    const int lane = tid & 31;
    const int wid  = tid >> 5;
    const int warprow = wid >> 2;          // 0 = hi rows 0-63, 1 = lo rows 64-127
    const int warpcol = wid & 3;
    const int m_warp = warprow * 64;
    const int n_warp = warpcol * 32;
    const uint32_t sb = s2u32(smem);
    const int C = xchunks + hchunks;

    float acc[4][4][4];
    #pragma unroll
    for (int mt = 0; mt < 4; mt++)
        #pragma unroll
        for (int nt = 0; nt < 4; nt++)
            #pragma unroll
            for (int i = 0; i < 4; i++) acc[mt][nt][i] = 0.f;

    auto load_stage = [&](int st, int c) {
        uint32_t abase = sb + st * STAGE_BYTES;
        uint32_t bbase = abase + 16384;
        const char* asrc; size_t astr;
        if (c < xchunks) { asrc = (const char*)xpart + (size_t)c * 128; astr = (size_t)xstride * 2; }
        else { asrc = (const char*)hpart + (size_t)(c - xchunks) * 128; astr = (size_t)hstride * 2; }
        const char* bsrc = (const char*)wbase
                         + ((size_t)blockIdx.x * 128 * wKc + (size_t)c * 64) * 2;
        const size_t bstr = (size_t)wKc * 2;
        #pragma unroll
        for (int i = 0; i < 4; i++) {
            int g = i * 256 + tid;          // 0..1023
            int row = g >> 3, col = g & 7;
            uint32_t off = (uint32_t)(row * 128 + col * 16);
            cpasync16(abase + SW128(off), asrc + (size_t)row * astr + col * 16);
            cpasync16(bbase + SW128(off), bsrc + (size_t)row * bstr + col * 16);
        }
        asm volatile("cp.async.commit_group;" ::: "memory");
    };

    load_stage(0, 0);

    for (int c = 0; c < C; c++) {
        if (c + 1 < C) {
            load_stage((c + 1) & 1, c + 1);
            asm volatile("cp.async.wait_group 1;" ::: "memory");
        } else {
            asm volatile("cp.async.wait_group 0;" ::: "memory");
        }
        __syncthreads();

        uint32_t abase = sb + (c & 1) * STAGE_BYTES;
        uint32_t bbase = abase + 16384;
        #pragma unroll
        for (int ks = 0; ks < 4; ks++) {
            int kb = ks * 32 + (lane >> 4) * 16;     // byte col within 128B row
            uint32_t af[4][4];
            #pragma unroll
            for (int mt = 0; mt < 4; mt++) {
                uint32_t off = (uint32_t)((m_warp + mt * 16 + (lane & 15)) * 128 + kb);
                ldm_x4(af[mt][0], af[mt][1], af[mt][2], af[mt][3], abase + SW128(off));
            }
            uint32_t bf[4][2];
            #pragma unroll
            for (int np = 0; np < 2; np++) {
                uint32_t off = (uint32_t)((n_warp + np * 16 + (lane & 15)) * 128 + kb);
                uint32_t r0, r1, r2, r3;
                ldm_x4(r0, r1, r2, r3, bbase + SW128(off));
                bf[np * 2][0] = r0; bf[np * 2 + 1][0] = r1;
                bf[np * 2][1] = r2; bf[np * 2 + 1][1] = r3;
            }
            #pragma unroll
            for (int mt = 0; mt < 4; mt++)
                #pragma unroll
                for (int nt = 0; nt < 4; nt++)
                    mma16816(acc[mt][nt], af[mt][0], af[mt][1], af[mt][2], af[mt][3],
                             bf[nt][0], bf[nt][1]);
        }
        __syncthreads();
    }

    // reduce partials into S_hi / S_lo (stride 68 floats -> conflict-free)
    float* S_hi = (float*)(smem + 2 * STAGE_BYTES);
    float* S_lo = S_hi + 64 * S_STRIDE;
    {
        float* Sw = (warprow == 0) ? S_hi : S_lo;
        int hrow = lane >> 2, head = lane & 3;
        #pragma unroll
        for (int mt = 0; mt < 4; mt++) {
            #pragma unroll
            for (int nt = 0; nt < 4; nt++) {
                int jj = warpcol * 4 + nt;
                int b0 = mt * 16 + hrow;
                if (warprow == 0) {
                    Sw[b0 * S_STRIDE + jj * 4 + head] = acc[mt][nt][0] + acc[mt][nt][1];
                    Sw[(b0 + 8) * S_STRIDE + jj * 4 + head] = acc[mt][nt][2] + acc[mt][nt][3];
                } else {
                    Sw[b0 * S_STRIDE + jj * 4 + head] = acc[mt][nt][0];
                    Sw[(b0 + 8) * S_STRIDE + jj * 4 + head] = acc[mt][nt][2];
                }
            }
        }
    }
    __syncthreads();

    const float ts = tsp[sidx];
    #pragma unroll
    for (int it = 0; it < 4; it++) {
        int pair = tid + it * 256;          // 0..1023
        int b = pair >> 4;
        int jj = pair & 15;
        int j = blockIdx.x * 16 + jj;
        if (j >= N) continue;
        const float* Ph = S_hi + b * S_STRIDE + jj * 4;
        const float* Pl = S_lo + b * S_STRIDE + jj * 4;
        float a0 = Ph[0] + Pl[0];
        float a1 = Ph[1] + Pl[1];
        float a2 = Ph[2] + Pl[2];
        float a3 = Ph[3] + Pl[3];
        float g    = tanhf(a0 + bg[j]);
        float hh   = tanhf(a1 + bh[j]);
        float pre  = (a2 + bfg[j]) + ts * (a3 + bfh[j]);
        float gate = 1.f / (1.f + expf(-pre));
        float o    = g * (1.f - gate) + hh * gate;
        __nv_bfloat16 ohi = __float2bfloat16(o);
        __nv_bfloat16 olo = __float2bfloat16(o - __bfloat162float(ohi));
        if (znx) {
            znx[(size_t)b * znx_stride + j] = ohi;
            znx[(size_t)(b + 64) * znx_stride + j] = olo;
        }
        zsh[(size_t)b * zsh_stride + j] = ohi;
        zsh[(size_t)(b + 64) * zsh_stride + j] = olo;
        if (yp)  yp[(size_t)b * (SEQ * MOTOR) + j] = o;
        if (hfp) hfp[(size_t)b * NUNITS + hoff + j] = o;
    }
}

// ---------------- host ----------------
extern "C" void kernel_launch(void* const* d_in, const int* in_sizes, int n_in,
                              void* d_out, int out_size)
{
    const float* x   = (const float*)d_in[0];
    const float* h0  = (const float*)d_in[1];
    const float* ts  = (const float*)d_in[2];
    const float *Wg1=(const float*)d_in[3], *Wh1=(const float*)d_in[4],
                *Wfg1=(const float*)d_in[5], *Wfh1=(const float*)d_in[6],
                *bg1=(const float*)d_in[7], *bh1=(const float*)d_in[8],
                *bfg1=(const float*)d_in[9], *bfh1=(const float*)d_in[10],
                *m1=(const float*)d_in[11];
    const float *Wg2=(const float*)d_in[12], *Wh2=(const float*)d_in[13],
                *Wfg2=(const float*)d_in[14], *Wfh2=(const float*)d_in[15],
                *bg2=(const float*)d_in[16], *bh2=(const float*)d_in[17],
                *bfg2=(const float*)d_in[18], *bfh2=(const float*)d_in[19],
                *m2=(const float*)d_in[20];
    const float *Wg3=(const float*)d_in[21], *Wh3=(const float*)d_in[22],
                *Wfg3=(const float*)d_in[23], *Wfh3=(const float*)d_in[24],
                *bg3=(const float*)d_in[25], *bh3=(const float*)d_in[26],
                *bfg3=(const float*)d_in[27], *bfh3=(const float*)d_in[28],
                *m3=(const float*)d_in[29];
    float* out = (float*)d_out;

    __nv_bfloat16 *wb1, *wb2, *wb3, *x1, *z1h, *z2x, *z2h, *z3x, *z3h;
    cudaGetSymbolAddress((void**)&wb1, g_wb1);
    cudaGetSymbolAddress((void**)&wb2, g_wb2);
    cudaGetSymbolAddress((void**)&wb3, g_wb3);
    cudaGetSymbolAddress((void**)&x1,  g_x1);
    cudaGetSymbolAddress((void**)&z1h, g_z1h);
    cudaGetSymbolAddress((void**)&z2x, g_z2x);
    cudaGetSymbolAddress((void**)&z2h, g_z2h);
    cudaGetSymbolAddress((void**)&z3x, g_z3x);
    cudaGetSymbolAddress((void**)&z3h, g_z3h);

    cudaFuncSetAttribute(cell_mma_kernel, cudaFuncAttributeMaxDynamicSharedMemorySize,
                         SMEM_TOTAL);

    prep_w_kernel<<<JT1 * 64, 256>>>(Wg1, Wh1, Wfg1, Wfh1, m1, wb1,
                                     INTER, IN_F + INTER, IN_F, IN_F, INTER, KC1);
    prep_w_kernel<<<JT2 * 64, 256>>>(Wg2, Wh2, Wfg2, Wfh2, m2, wb2,
                                     CMD, INTER + CMD, INTER, XPAD2, CMD, KC2);
    prep_w_kernel<<<JT3 * 64, 256>>>(Wg3, Wh3, Wfg3, Wfh3, m3, wb3,
                                     MOTOR, CMD + MOTOR, CMD, XPAD3, MOTOR, KC3);
    prep_x_kernel<<<(BATCH * SEQ * IN_F) / 256, 256>>>(x, x1);
    prep_h0_kernel<<<(BATCH * NUNITS) / 256, 256>>>(h0, z1h, z2h, z3h);

    int p = 0;
    for (int s = 0; s < SEQ; s++) {
        const __nv_bfloat16* xt = x1 + (size_t)s * 128 * IN_F;
        float* hfp = (s == SEQ - 1) ? (out + YSZ) : nullptr;
        cell_mma_kernel<<<JT1, 256, SMEM_TOTAL>>>(
            xt, IN_F, XCH1, z1h + (size_t)p * 128 * HPAD1, HPAD1, HCH1,
            wb1, KC1, bg1, bh1, bfg1, bfh1, ts, s, INTER,
            z2x, XPAD2, z1h + (size_t)(1 - p) * 128 * HPAD1, HPAD1,
            nullptr, hfp, 0);
        cell_mma_kernel<<<JT2, 256, SMEM_TOTAL>>>(
            z2x, XPAD2, XCH2, z2h + (size_t)p * 128 * HPAD2, HPAD2, HCH2,
            wb2, KC2, bg2, bh2, bfg2, bfh2, ts, s, CMD,
            z3x, XPAD3, z2h + (size_t)(1 - p) * 128 * HPAD2, HPAD2,
            nullptr, hfp, INTER);
        cell_mma_kernel<<<JT3, 256, SMEM_TOTAL>>>(
            z3x, XPAD3, XCH3, z3h + (size_t)p * 128 * HPAD3, HPAD3, HCH3,
            wb3, KC3, bg3, bh3, bfg3, bfh3, ts, s, MOTOR,
            nullptr, 0, z3h + (size_t)(1 - p) * 128 * HPAD3, HPAD3,
            out + (size_t)s * MOTOR, hfp, INTER + CMD);
        p ^= 1;
    }
}